// round 3
// baseline (speedup 1.0000x reference)
#include <cuda_runtime.h>
#include <cuda_bf16.h>

// Focal BCE with logits, mean-reduced.
//   loss(x,t) = a * (1-q)^gamma * (-ln q),  q = sigmoid((t==1)? x : -x),
//               a = (t==1)? ALPHA : 1-ALPHA
// Rewritten with sp = softplus(-y) = -ln q:
//   (1-q)^gamma = exp(-gamma * softplus(y)) = exp(-gamma * (y + sp))
//   loss = a * exp(-gamma*(y+sp)) * sp
// => 3 MUFU ops per element (EX2, LG2, EX2); kernel stays HBM-bound.

#define FOCAL_GAMMA 0.2f
#define FOCAL_ALPHA 0.6f

__device__ __forceinline__ float focal_elem(float x, int t) {
    bool pos = (t == 1);
    float y = pos ? x : -x;
    float a = pos ? FOCAL_ALPHA : (1.0f - FOCAL_ALPHA);
    float u  = __expf(-y);                        // e^{-y}
    float sp = __logf(1.0f + u);                  // softplus(-y) = -ln(q)
    float w  = __expf(-FOCAL_GAMMA * (y + sp));   // (1-q)^gamma
    return a * w * sp;
}

__global__ void focal_zero_kernel(float* out) { *out = 0.0f; }

__global__ void __launch_bounds__(256)
focal_main_kernel(const float4* __restrict__ x4,
                  const int4*  __restrict__ t4,
                  const float* __restrict__ x_scalar,
                  const int*   __restrict__ t_scalar,
                  float* __restrict__ out,
                  int n4, long long n_total, float inv_total) {
    float acc = 0.0f;
    int stride = gridDim.x * blockDim.x;
    int gid = blockIdx.x * blockDim.x + threadIdx.x;

    // Main loop: two float4/int4 pairs per iteration -> 4 independent
    // LDG.E.128 issued back-to-back before any consumption (MLP >= 4).
    int i = gid;
    for (; i + stride < n4; i += 2 * stride) {
        float4 xa = x4[i];
        int4   ta = t4[i];
        float4 xb = x4[i + stride];
        int4   tb = t4[i + stride];
        acc += focal_elem(xa.x, ta.x);
        acc += focal_elem(xa.y, ta.y);
        acc += focal_elem(xa.z, ta.z);
        acc += focal_elem(xa.w, ta.w);
        acc += focal_elem(xb.x, tb.x);
        acc += focal_elem(xb.y, tb.y);
        acc += focal_elem(xb.z, tb.z);
        acc += focal_elem(xb.w, tb.w);
    }
    if (i < n4) {
        float4 xa = x4[i];
        int4   ta = t4[i];
        acc += focal_elem(xa.x, ta.x);
        acc += focal_elem(xa.y, ta.y);
        acc += focal_elem(xa.z, ta.z);
        acc += focal_elem(xa.w, ta.w);
    }

    // Scalar tail (n_total % 4 != 0).
    long long tail_start = (long long)n4 * 4;
    for (long long j = tail_start + gid; j < n_total; j += stride) {
        acc += focal_elem(x_scalar[j], t_scalar[j]);
    }

    // Intra-warp reduction
    #pragma unroll
    for (int off = 16; off > 0; off >>= 1)
        acc += __shfl_xor_sync(0xffffffffu, acc, off);

    __shared__ float warp_sums[8];
    int lane = threadIdx.x & 31;
    int wid  = threadIdx.x >> 5;
    if (lane == 0) warp_sums[wid] = acc;
    __syncthreads();

    if (wid == 0) {
        acc = (lane < (blockDim.x >> 5)) ? warp_sums[lane] : 0.0f;
        #pragma unroll
        for (int off = 4; off > 0; off >>= 1)
            acc += __shfl_xor_sync(0xffffffffu, acc, off);
        if (lane == 0)
            atomicAdd(out, acc * inv_total);
    }
}

extern "C" void kernel_launch(void* const* d_in, const int* in_sizes, int n_in,
                              void* d_out, int out_size) {
    const float* logits = (const float*)d_in[0];
    const int*   target = (const int*)d_in[1];
    float* out = (float*)d_out;

    long long n_total = (long long)in_sizes[0];
    int n4 = (int)(n_total / 4);
    float inv_total = (float)(1.0 / (double)n_total);

    // Full residency in one wave: ~8 CTAs/SM of 256 threads.
    int blocks = 148 * 8;
    long long max_useful = (n_total + 255) / 256;
    if ((long long)blocks > max_useful) blocks = (int)max_useful;
    if (blocks < 1) blocks = 1;

    focal_zero_kernel<<<1, 1>>>(out);
    focal_main_kernel<<<blocks, 256>>>(
        (const float4*)logits, (const int4*)target,
        logits, target, out, n4, n_total, inv_total);
}